// round 10
// baseline (speedup 1.0000x reference)
#include <cuda_runtime.h>
#include <cstdint>

#define B_   32
#define G_   2704
#define D_   1024
#define L_   20
#define HID_ 512
#define K_   128
#define OUTROWS (K_ + L_)     // 148
#define BOXSTRIDE 18          // A*C = 3*6

// ---------------- scratch (no allocations allowed) ----------------
__device__ int   g_sel_by_rank[B_ * K_];
__device__ int   g_idx[B_ * K_];
__device__ float g_gathered[B_ * K_ * D_];   // 16.8 MB, [B*K, D] row-major

// monotone float->uint mapping
__device__ __forceinline__ unsigned int ord32(float f) {
    unsigned int u = __float_as_uint(f);
    return (u & 0x80000000u) ? ~u : (u | 0x80000000u);
}

// ---------------------------------------------------------------------------
// Kernel 1: per-batch scores -> exact top-K via rank counting. (unchanged)
// ---------------------------------------------------------------------------
__global__ void __launch_bounds__(512) topk_kernel(const float* __restrict__ boxes) {
    __shared__ __align__(16) unsigned long long keys[G_];
    int b    = blockIdx.x;
    int tid  = threadIdx.x;
    const float* bb = boxes + (size_t)b * G_ * BOXSTRIDE;

    for (int g = tid; g < G_; g += 512) {
        int base = g * BOXSTRIDE;
        float sc = (bb[base + 4] + bb[base + 10] + bb[base + 16]) * (1.0f / 3.0f);
        keys[g] = ((unsigned long long)ord32(sc) << 32) | (unsigned int)(G_ - g);
    }
    __syncthreads();

    int q = blockIdx.y * 512 + tid;
    if (q < G_) {
        unsigned long long my = keys[q];
        int cnt = 0;
        #pragma unroll 4
        for (int j = 0; j < G_ / 2; j++) {
            ulonglong2 kv = *(const ulonglong2*)&keys[2 * j];
            cnt += (kv.x > my);
            cnt += (kv.y > my);
        }
        if (cnt < K_) g_sel_by_rank[b * K_ + cnt] = q;
    }
}

// ---------------------------------------------------------------------------
// Kernel 2: ascending reorder + sel_boxes. (unchanged)
// ---------------------------------------------------------------------------
__global__ void __launch_bounds__(K_) order_kernel(const float* __restrict__ boxes,
                                                   float* __restrict__ out_boxes) {
    __shared__ int gs[K_];
    int b = blockIdx.x, t = threadIdx.x;
    int g = g_sel_by_rank[b * K_ + t];
    gs[t] = g;
    __syncthreads();
    int pos = 0;
    #pragma unroll 8
    for (int j = 0; j < K_; j++) pos += (gs[j] < g);
    g_idx[b * K_ + pos] = g;

    const float* src = boxes + ((size_t)b * G_ + g) * BOXSTRIDE;
    float*       dst = out_boxes + ((size_t)b * K_ + pos) * BOXSTRIDE;
    #pragma unroll
    for (int c = 0; c < BOXSTRIDE; c++) dst[c] = src[c];
}

// ---------------------------------------------------------------------------
// Kernel 3: gather selected feature columns. (unchanged)
// ---------------------------------------------------------------------------
__global__ void __launch_bounds__(256) gather_kernel(const float* __restrict__ feature) {
    int i = blockIdx.x * 256 + threadIdx.x;
    int d = i & (D_ - 1);
    int k = (i >> 10) & (K_ - 1);
    int b = i >> 17;
    int g = g_idx[b * K_ + k];
    g_gathered[i] = __ldg(&feature[((size_t)(b * D_ + d)) * G_ + g]);
}

// ---------------------------------------------------------------------------
// Kernel 4: fp32 FFMA2 GEMM, v2.
//  - B stored DUPLICATED in SMEM ([b,b] pairs): B fragments load as LDS.128
//    of ready f32x2 operands; the 4 dependent mov.b64/kk are gone.
//  - Explicit register double-buffering of A/B fragments across kk: fragment
//    loads for kk+1 issue while the 16 FFMA2 of kk drain -> LDS latency off
//    the critical path (ncu showed fma pipe 50.6% idle-half from these stalls).
//  Tiles/grid unchanged: 128x64x16, 256 threads, 8x4 microtile (4 m-pairs x 4 n).
// ---------------------------------------------------------------------------
#define BM 128
#define BN 64
#define BKD 16
#define ASTR (BM + 4)   // pad kills STS bank conflicts, keeps 16B align

__global__ void __launch_bounds__(256, 2) gemm_kernel(
    const float* __restrict__ Am, const float* __restrict__ Wm,
    const float* __restrict__ bias, float* __restrict__ out,
    int Kd, int rowsPerBatch, int rowOffset)
{
    if (Am == nullptr) Am = g_gathered;

    __shared__ __align__(16) float As[2][BKD][ASTR];
    __shared__ __align__(16) float Bs[2][BKD][2 * BN];   // duplicated pairs

    int tid   = threadIdx.x;
    int mTile = blockIdx.y * BM;
    int nTile = blockIdx.x * BN;

    int tx = tid & 15, ty = tid >> 4;
    int m0 = ty * 8,   n0 = tx * 4;

    // load-phase mapping
    int ar = tid >> 2;            // 0..63 (rows ar and ar+64)
    int ac = (tid & 3) * 4;       // 0,4,8,12
    int br = tid >> 4;            // 0..15
    int bc = (tid & 15) * 4;      // 0..60

    const float* Aptr0 = Am + (size_t)(mTile + ar)      * Kd + ac;
    const float* Aptr1 = Am + (size_t)(mTile + ar + 64) * Kd + ac;
    const float* Bptr  = Wm + (size_t)br * HID_ + nTile + bc;

    unsigned long long acc[4][4];
    #pragma unroll
    for (int i = 0; i < 4; i++)
        #pragma unroll
        for (int j = 0; j < 4; j++) acc[i][j] = 0ULL;

    int nk = Kd / BKD;

    // prologue: fill buffer 0
    float4 a0 = *(const float4*)(Aptr0);
    float4 a1 = *(const float4*)(Aptr1);
    float4 bv = *(const float4*)(Bptr);
    As[0][ac + 0][ar]      = a0.x; As[0][ac + 1][ar]      = a0.y;
    As[0][ac + 2][ar]      = a0.z; As[0][ac + 3][ar]      = a0.w;
    As[0][ac + 0][ar + 64] = a1.x; As[0][ac + 1][ar + 64] = a1.y;
    As[0][ac + 2][ar + 64] = a1.z; As[0][ac + 3][ar + 64] = a1.w;
    *(float4*)&Bs[0][br][2 * bc]     = make_float4(bv.x, bv.x, bv.y, bv.y);
    *(float4*)&Bs[0][br][2 * bc + 4] = make_float4(bv.z, bv.z, bv.w, bv.w);
    __syncthreads();

    unsigned long long af[2][4], bf[2][4];

    for (int kb = 0; kb < nk; kb++) {
        int cur = kb & 1, nxt = cur ^ 1;
        bool more = (kb + 1 < nk);

        if (more) {   // global prefetch for tile kb+1 (drains under compute)
            a0 = *(const float4*)(Aptr0 + (kb + 1) * BKD);
            a1 = *(const float4*)(Aptr1 + (kb + 1) * BKD);
            bv = *(const float4*)(Bptr + (size_t)(kb + 1) * BKD * HID_);
        }

        // fragment prologue: kk = 0
        {
            ulonglong2 p0 = *(const ulonglong2*)&As[cur][0][m0];
            ulonglong2 p1 = *(const ulonglong2*)&As[cur][0][m0 + 4];
            af[0][0] = p0.x; af[0][1] = p0.y; af[0][2] = p1.x; af[0][3] = p1.y;
            ulonglong2 q0 = *(const ulonglong2*)&Bs[cur][0][2 * n0];
            ulonglong2 q1 = *(const ulonglong2*)&Bs[cur][0][2 * n0 + 4];
            bf[0][0] = q0.x; bf[0][1] = q0.y; bf[0][2] = q1.x; bf[0][3] = q1.y;
        }

        #pragma unroll
        for (int kk = 0; kk < BKD; kk++) {
            int pp = kk & 1, np = pp ^ 1;
            if (kk + 1 < BKD) {   // prefetch fragments for kk+1
                ulonglong2 p0 = *(const ulonglong2*)&As[cur][kk + 1][m0];
                ulonglong2 p1 = *(const ulonglong2*)&As[cur][kk + 1][m0 + 4];
                af[np][0] = p0.x; af[np][1] = p0.y; af[np][2] = p1.x; af[np][3] = p1.y;
                ulonglong2 q0 = *(const ulonglong2*)&Bs[cur][kk + 1][2 * n0];
                ulonglong2 q1 = *(const ulonglong2*)&Bs[cur][kk + 1][2 * n0 + 4];
                bf[np][0] = q0.x; bf[np][1] = q0.y; bf[np][2] = q1.x; bf[np][3] = q1.y;
            }
            #pragma unroll
            for (int i = 0; i < 4; i++)
                #pragma unroll
                for (int j = 0; j < 4; j++)
                    asm("fma.rn.f32x2 %0, %1, %2, %0;"
                        : "+l"(acc[i][j]) : "l"(af[pp][i]), "l"(bf[pp][j]));
        }

        if (more) {   // STS into the other buffer, overlapped with tail of compute
            As[nxt][ac + 0][ar]      = a0.x; As[nxt][ac + 1][ar]      = a0.y;
            As[nxt][ac + 2][ar]      = a0.z; As[nxt][ac + 3][ar]      = a0.w;
            As[nxt][ac + 0][ar + 64] = a1.x; As[nxt][ac + 1][ar + 64] = a1.y;
            As[nxt][ac + 2][ar + 64] = a1.z; As[nxt][ac + 3][ar + 64] = a1.w;
            *(float4*)&Bs[nxt][br][2 * bc]     = make_float4(bv.x, bv.x, bv.y, bv.y);
            *(float4*)&Bs[nxt][br][2 * bc + 4] = make_float4(bv.z, bv.z, bv.w, bv.w);
        }
        __syncthreads();
    }

    float4 bias4 = *(const float4*)&bias[nTile + n0];
    #pragma unroll
    for (int i = 0; i < 4; i++) {
        float2 v[4];
        #pragma unroll
        for (int j = 0; j < 4; j++) v[j] = *(float2*)&acc[i][j];

        int m    = mTile + m0 + 2 * i;        // even row of the pair
        int bat  = m / rowsPerBatch;
        int r    = m - bat * rowsPerBatch;
        float* o0 = out + (size_t)bat * (OUTROWS * HID_)
                        + (size_t)(rowOffset + r) * HID_ + nTile + n0;
        *(float4*)o0 = make_float4(v[0].x + bias4.x, v[1].x + bias4.y,
                                   v[2].x + bias4.z, v[3].x + bias4.w);

        int m1   = m + 1;
        int bat1 = m1 / rowsPerBatch;
        int r1   = m1 - bat1 * rowsPerBatch;
        float* o1 = out + (size_t)bat1 * (OUTROWS * HID_)
                        + (size_t)(rowOffset + r1) * HID_ + nTile + n0;
        *(float4*)o1 = make_float4(v[0].y + bias4.x, v[1].y + bias4.y,
                                   v[2].y + bias4.z, v[3].y + bias4.w);
    }
}

// ---------------------------------------------------------------------------
// Launch: out = [ concat(linear_feature, linear_text) : B x 148 x 512,
//                 sel_boxes : B x 128 x 3 x 6 ]  (tuple order, flattened)
// ---------------------------------------------------------------------------
extern "C" void kernel_launch(void* const* d_in, const int* in_sizes, int n_in,
                              void* d_out, int out_size) {
    const float* boxes   = (const float*)d_in[0];
    const float* feature = (const float*)d_in[1];
    const float* text    = (const float*)d_in[2];
    const float* W_vs    = (const float*)d_in[3];
    const float* b_vs    = (const float*)d_in[4];
    const float* W_tx    = (const float*)d_in[5];
    const float* b_tx    = (const float*)d_in[6];
    (void)in_sizes; (void)n_in; (void)out_size;

    float* out       = (float*)d_out;
    float* out_boxes = out + (size_t)B_ * OUTROWS * HID_;

    topk_kernel <<<dim3(B_, 6), 512>>>(boxes);
    order_kernel<<<B_, K_>>>(boxes, out_boxes);
    gather_kernel<<<(B_ * K_ * D_) / 256, 256>>>(feature);

    // linear_feature: [B*K, 1024] @ [1024, 512] -> rows 0..127 of each batch
    gemm_kernel<<<dim3(HID_ / BN, (B_ * K_) / BM), 256>>>(
        nullptr, W_vs, b_vs, out, D_, K_, 0);

    // linear_text: [B*L, 512] @ [512, 512] -> rows 128..147 of each batch
    gemm_kernel<<<dim3(HID_ / BN, (B_ * L_) / BM), 256>>>(
        text, W_tx, b_tx, out, HID_, L_, K_);
}